// round 15
// baseline (speedup 1.0000x reference)
#include <cuda_runtime.h>
#include <cstdint>

// HyperComplexAdapterBlock: y = phm_up(gelu_new(phm_down(x))), rank-1 PHM.
// R15 = R14 + true TMA double-buffering: 4 token slots per warp, chunk A ->
// slots{0,1}, chunk B -> slots{2,3}, wait_group.read<=1 always targets a
// group committed a full chunk + front-end earlier (R14 waited ~40cyc after
// commit -> per-iter TMA stall). To fit 49KB stage: Ld/Ru broadcast tables
// read via __ldg straight from the ORIGINAL global layout (fixed (i,m) ->
// 8 consecutive granules = 1 wavefront L1-hit, same cost as smem). Both
// chunk tokens contiguous -> single 6144B bulk store. 4 CTAs/SM, 16 warps.

typedef unsigned long long u64;

__device__ __forceinline__ u64 fma2(u64 a, u64 b, u64 c) {
    u64 d;
    asm("fma.rn.f32x2 %0, %1, %2, %3;" : "=l"(d) : "l"(a), "l"(b), "l"(c));
    return d;
}
__device__ __forceinline__ u64 pk2(float lo, float hi) {
    u64 r; asm("mov.b64 %0, {%1, %2};" : "=l"(r) : "f"(lo), "f"(hi));
    return r;
}
__device__ __forceinline__ float sum2(u64 v) {
    float a, b; asm("mov.b64 {%0, %1}, %2;" : "=f"(a), "=f"(b) : "l"(v));
    return a + b;
}
__device__ __forceinline__ float tanh_fast(float x) {
    float y; asm("tanh.approx.f32 %0, %1;" : "=f"(y) : "f"(x));
    return y;
}
__device__ __forceinline__ void bulk_store(void* gdst, uint32_t ssrc, int bytes) {
    asm volatile("cp.async.bulk.global.shared::cta.bulk_group [%0], [%1], %2;"
                 :: "l"(gdst), "r"(ssrc), "r"(bytes) : "memory");
}

#define NW 4          // warps per CTA
#define NT 128        // threads per CTA
#define TPI 4         // tokens per warp-iteration
#define NSLOT 4       // stage token slots per warp (2 chunks x 2 tokens)

// dynamic smem layout (bytes)
#define OFF_STG   0
#define SZ_STG    (NW * NSLOT * 192 * 16)         // 49152
#define OFF_PRL   (OFF_STG + SZ_STG)              // 192 float2 (Rd,Lu), z-keyed
#define OFF_BUT   (OFF_PRL + 1536)                // 192 f4 bias_u, [m*32+l]
#define OFF_RRD   (OFF_BUT + 3072)                // 64 f rule_d
#define OFF_RRU   (OFF_RRD + 256)                 // 64 f rule_u
#define SMEM_TOTAL (OFF_RRU + 256)                // 54272

__global__ __launch_bounds__(NT, 4)
void phm_fused_kernel(const float* __restrict__ x,
                      const float* __restrict__ rule_d,
                      const float* __restrict__ Ld,
                      const float* __restrict__ Rd,
                      const float* __restrict__ bd,
                      const float* __restrict__ rule_u,
                      const float* __restrict__ Lu,
                      const float* __restrict__ Ru,
                      const float* __restrict__ bu,
                      float* __restrict__ out,
                      int ntok)
{
    extern __shared__ __align__(16) char smem[];
    ulonglong2* stg  = (ulonglong2*)(smem + OFF_STG);
    float2*     pRLT = (float2*)(smem + OFF_PRL);
    ulonglong2* sBuT = (ulonglong2*)(smem + OFF_BUT);
    float*      sRd  = (float*)(smem + OFF_RRD);
    float*      sRu  = (float*)(smem + OFF_RRU);

    const int tid = threadIdx.x;
    const ulonglong2* Ld2 = (const ulonglong2*)Ld;
    const ulonglong2* Ru2 = (const ulonglong2*)Ru;
    const ulonglong2* bu2 = (const ulonglong2*)bu;

    for (int idx = tid; idx < 192; idx += NT) {
        int i = idx / 48, q = idx % 48;
        // z-keyed table (kk = q/6, j = q%6): scalar q = 6kk + j
        pRLT[(i*6 + (q % 6))*8 + (q / 6)] = make_float2(Rd[idx], Lu[idx]);
        // bias_u: sBuT[m*32 + l] = bu4[48*(l/8) + (l%8) + 8m]
        int m = idx / 32, ll = idx % 32;
        sBuT[idx] = bu2[48*(ll >> 3) + (ll & 7) + 8*m];
    }
    for (int idx = tid; idx < 64; idx += NT) {
        sRd[idx] = rule_d[idx];
        sRu[idx] = rule_u[idx];
    }
    __syncthreads();

    const int l = tid & 31;
    const int w = tid >> 5;
    const int g = l >> 3;        // group: a on input side, c on z/output side
    const int k = l & 7;

    float biasD[6];
#pragma unroll
    for (int j = 0; j < 6; j++)
        biasD[j] = bd[6*l + j];   // = bd[48g + 6k + j]

    const ulonglong2* x2 = (const ulonglong2*)x;
    char* outc = (char*)out;
    ulonglong2* stgW = stg + (size_t)w * (NSLOT * 192);
    const uint32_t stgW_s = (uint32_t)__cvta_generic_to_shared(stgW);

    const int gwarp = blockIdx.x * NW + w;
    const int nwarp = gridDim.x * NW;
    const int fbase = 48*g + k;  // lane's granule base (input AND output)

    for (int base = gwarp * TPI; base < ntok; base += nwarp * TPI) {
        int row[TPI];
#pragma unroll
        for (int tt = 0; tt < TPI; tt++) {
            int t = base + tt; if (t > ntok - 1) t = ntok - 1;
            row[tt] = t * 192 + fbase;
        }

        // ---- down stage 1: direct stride-8 loads (4 full 128B lines per
        //      LDG across the warp); Ld weights via 1-wf L1-hit __ldg ----
        u64 si2[TPI][4];
#pragma unroll
        for (int tt = 0; tt < TPI; tt++)
#pragma unroll
            for (int i = 0; i < 4; i++) si2[tt][i] = 0ull;

#pragma unroll
        for (int m = 0; m < 6; m++) {
            ulonglong2 u[TPI];
#pragma unroll
            for (int tt = 0; tt < TPI; tt++)
                u[tt] = x2[row[tt] + 8*m];
#pragma unroll
            for (int i = 0; i < 4; i++) {
                ulonglong2 wv = __ldg(&Ld2[i*48 + 8*m + k]);  // 1 line/warp
#pragma unroll
                for (int tt = 0; tt < TPI; tt++) {
                    si2[tt][i] = fma2(u[tt].x, wv.x, si2[tt][i]);
                    si2[tt][i] = fma2(u[tt].y, wv.y, si2[tt][i]);
                }
            }
        }
        // butterfly within 8-lane groups -> group-uniform si
        float si[TPI][4];
#pragma unroll
        for (int tt = 0; tt < TPI; tt++)
#pragma unroll
            for (int i = 0; i < 4; i++) {
                float v = sum2(si2[tt][i]);
                v += __shfl_xor_sync(0xffffffffu, v, 4);
                v += __shfl_xor_sync(0xffffffffu, v, 2);
                v += __shfl_xor_sync(0xffffffffu, v, 1);
                si[tt][i] = v;
            }

        // ---- down stage 2: weighted rotate (3 SHFL per i) ----
        float tD[TPI][4];
#pragma unroll
        for (int tt = 0; tt < TPI; tt++)
#pragma unroll
            for (int i = 0; i < 4; i++)
                tD[tt][i] = sRd[i*16 + 5*g] * si[tt][i];
#pragma unroll
        for (int m = 1; m < 4; m++)
#pragma unroll
            for (int i = 0; i < 4; i++) {
                float r = sRd[i*16 + ((g ^ m) << 2) + g];
#pragma unroll
                for (int tt = 0; tt < TPI; tt++)
                    tD[tt][i] = fmaf(r, __shfl_xor_sync(0xffffffffu, si[tt][i], m*8),
                                     tD[tt][i]);
            }

        // ---- fused z -> gelu_new -> up stage 1 (s2); lane z: q = 6k+j ----
        float s2[TPI][4];
#pragma unroll
        for (int tt = 0; tt < TPI; tt++)
#pragma unroll
            for (int i = 0; i < 4; i++) s2[tt][i] = 0.f;

#pragma unroll
        for (int j = 0; j < 6; j++) {
            float2 rl[4];
#pragma unroll
            for (int i = 0; i < 4; i++) rl[i] = pRLT[(i*6 + j)*8 + k];
            float zv[TPI];
#pragma unroll
            for (int tt = 0; tt < TPI; tt++) zv[tt] = biasD[j];
#pragma unroll
            for (int i = 0; i < 4; i++)
#pragma unroll
                for (int tt = 0; tt < TPI; tt++)
                    zv[tt] = fmaf(tD[tt][i], rl[i].x, zv[tt]);
#pragma unroll
            for (int tt = 0; tt < TPI; tt++) {
                float z   = zv[tt];
                float arg = 0.7978845608028654f * fmaf(0.044715f*z, z*z, z);
                float h   = 0.5f * z;
                zv[tt] = fmaf(h, tanh_fast(arg), h);   // 0.5z(1+tanh)
            }
#pragma unroll
            for (int i = 0; i < 4; i++)
#pragma unroll
                for (int tt = 0; tt < TPI; tt++)
                    s2[tt][i] = fmaf(zv[tt], rl[i].y, s2[tt][i]);
        }
        // butterfly -> group-uniform s2
#pragma unroll
        for (int tt = 0; tt < TPI; tt++)
#pragma unroll
            for (int i = 0; i < 4; i++) {
                float v = s2[tt][i];
                v += __shfl_xor_sync(0xffffffffu, v, 4);
                v += __shfl_xor_sync(0xffffffffu, v, 2);
                v += __shfl_xor_sync(0xffffffffu, v, 1);
                s2[tt][i] = v;
            }

        // ---- up stage 2: weighted rotate ----
        float tU[TPI][4];
#pragma unroll
        for (int tt = 0; tt < TPI; tt++)
#pragma unroll
            for (int i = 0; i < 4; i++)
                tU[tt][i] = sRu[i*16 + 5*g] * s2[tt][i];
#pragma unroll
        for (int m = 1; m < 4; m++)
#pragma unroll
            for (int i = 0; i < 4; i++) {
                float r = sRu[i*16 + ((g ^ m) << 2) + g];
#pragma unroll
                for (int tt = 0; tt < TPI; tt++)
                    tU[tt][i] = fmaf(r, __shfl_xor_sync(0xffffffffu, s2[tt][i], m*8),
                                     tU[tt][i]);
            }

        // ---- output: two 2-token chunks into DISTINCT slot pairs
        //      ({0,1} then {2,3}); every wait targets a group committed a
        //      full chunk + front-end earlier -> no TMA stall ----
#pragma unroll
        for (int c0 = 0; c0 < TPI; c0 += 2) {
            u64 tUp[2][4];
#pragma unroll
            for (int cc = 0; cc < 2; cc++)
#pragma unroll
                for (int i = 0; i < 4; i++)
                    tUp[cc][i] = pk2(tU[c0+cc][i], tU[c0+cc][i]);

            // slots {c0, c0+1}: last used by the same chunk of the PREVIOUS
            // iteration (2 groups back) -> wait read<=1
            if (l == 0)
                asm volatile("cp.async.bulk.wait_group.read 1;" ::: "memory");
            __syncwarp();

#pragma unroll
            for (int m = 0; m < 6; m++) {
                ulonglong2 rv[4];
#pragma unroll
                for (int i = 0; i < 4; i++)
                    rv[i] = __ldg(&Ru2[i*48 + 8*m + k]);  // 1 line/warp
                ulonglong2 bb = sBuT[m*32 + l];           // 1-wf, linear
#pragma unroll
                for (int cc = 0; cc < 2; cc++) {
                    ulonglong2 o = bb;
#pragma unroll
                    for (int i = 0; i < 4; i++) {
                        o.x = fma2(tUp[cc][i], rv[i].x, o.x);
                        o.y = fma2(tUp[cc][i], rv[i].y, o.y);
                    }
                    stgW[(c0 + cc)*192 + fbase + 8*m] = o;  // conflict-free
                }
            }
            __syncwarp();
            asm volatile("fence.proxy.async.shared::cta;" ::: "memory");
            if (l == 0) {
                int t0 = base + c0;
                if (t0 + 1 < ntok)          // both tokens: one 6144B store
                    bulk_store(outc + (size_t)t0 * 3072,
                               stgW_s + c0 * 3072, 6144);
                else if (t0 < ntok)
                    bulk_store(outc + (size_t)t0 * 3072,
                               stgW_s + c0 * 3072, 3072);
                asm volatile("cp.async.bulk.commit_group;" ::: "memory");
            }
        }
    }
    // drain outstanding bulk stores before exit
    if (l == 0)
        asm volatile("cp.async.bulk.wait_group 0;" ::: "memory");
}

extern "C" void kernel_launch(void* const* d_in, const int* in_sizes, int n_in,
                              void* d_out, int out_size)
{
    const float* x      = (const float*)d_in[0];
    const float* rule_d = (const float*)d_in[1];
    const float* Ld     = (const float*)d_in[2];
    const float* Rd     = (const float*)d_in[3];
    const float* bd     = (const float*)d_in[4];
    const float* rule_u = (const float*)d_in[5];
    const float* Lu     = (const float*)d_in[6];
    const float* Ru     = (const float*)d_in[7];
    const float* bu     = (const float*)d_in[8];

    const int ntok = in_sizes[0] / 768;

    cudaFuncSetAttribute(phm_fused_kernel,
                         cudaFuncAttributeMaxDynamicSharedMemorySize,
                         SMEM_TOTAL);

    // 148 SMs * 4 CTAs (128 thr, 53KB smem each) = one full wave
    phm_fused_kernel<<<592, NT, SMEM_TOTAL>>>(x, rule_d, Ld, Rd, bd,
                                              rule_u, Lu, Ru, bu,
                                              (float*)d_out, ntok);
}

// round 16
// speedup vs baseline: 1.0298x; 1.0298x over previous
#include <cuda_runtime.h>
#include <cstdint>

// HyperComplexAdapterBlock: y = phm_up(gelu_new(phm_down(x))), rank-1 PHM.
// R16 = R14 (champion: direct stride-8 input LDG; smem weight tables;
// weighted-rotate shuffles; f32x2; tanh.approx; TPI=4; output via linear
// conflict-free STS -> TMA bulk store) with occupancy raised 5 -> 6 CTAs/SM:
// smem is only 35.8KB so 6 fit (215KB); the blocker was regs=96, so force
// an 85-reg cap via __launch_bounds__(128,6) (+ drop the row[] array to
// ease pressure). Grid is occupancy-adaptive and uses the REAL SM count
// (GB300 = 152, not 148 — previous rounds left 12 SMs underfilled).
// R15 lesson: keep weights in smem (__ldg blew regs to 128).

typedef unsigned long long u64;

__device__ __forceinline__ u64 fma2(u64 a, u64 b, u64 c) {
    u64 d;
    asm("fma.rn.f32x2 %0, %1, %2, %3;" : "=l"(d) : "l"(a), "l"(b), "l"(c));
    return d;
}
__device__ __forceinline__ u64 pk2(float lo, float hi) {
    u64 r; asm("mov.b64 %0, {%1, %2};" : "=l"(r) : "f"(lo), "f"(hi));
    return r;
}
__device__ __forceinline__ float sum2(u64 v) {
    float a, b; asm("mov.b64 {%0, %1}, %2;" : "=f"(a), "=f"(b) : "l"(v));
    return a + b;
}
__device__ __forceinline__ float tanh_fast(float x) {
    float y; asm("tanh.approx.f32 %0, %1;" : "=f"(y) : "f"(x));
    return y;
}
__device__ __forceinline__ void bulk_store(void* gdst, uint32_t ssrc, int bytes) {
    asm volatile("cp.async.bulk.global.shared::cta.bulk_group [%0], [%1], %2;"
                 :: "l"(gdst), "r"(ssrc), "r"(bytes) : "memory");
}

#define NW 4          // warps per CTA
#define NT 128        // threads per CTA
#define TPI 4         // tokens per warp-iteration
#define CHK 2         // tokens staged per output chunk
#define CPB 6         // target CTAs per SM (85-reg cap)

// dynamic smem layout (bytes)
#define OFF_STG   0
#define SZ_STG    (NW * CHK * 192 * 16)           // 24576 (linear token rows)
#define OFF_PLD   (OFF_STG + SZ_STG)              // 192 f4, (i*6+m)*8+k keyed
#define OFF_PRU   (OFF_PLD + 3072)                // 192 f4, (i*6+m)*8+k keyed
#define OFF_PRL   (OFF_PRU + 3072)                // 192 float2 (Rd,Lu), z-keyed
#define OFF_BUT   (OFF_PRL + 1536)                // 192 f4 bias_u, [m*32+l]
#define OFF_RRD   (OFF_BUT + 3072)                // 64 f rule_d
#define OFF_RRU   (OFF_RRD + 256)                 // 64 f rule_u
#define SMEM_TOTAL (OFF_RRU + 256)                // 35840

__global__ __launch_bounds__(NT, CPB)
void phm_fused_kernel(const float* __restrict__ x,
                      const float* __restrict__ rule_d,
                      const float* __restrict__ Ld,
                      const float* __restrict__ Rd,
                      const float* __restrict__ bd,
                      const float* __restrict__ rule_u,
                      const float* __restrict__ Lu,
                      const float* __restrict__ Ru,
                      const float* __restrict__ bu,
                      float* __restrict__ out,
                      int ntok)
{
    extern __shared__ __align__(16) char smem[];
    ulonglong2* stg  = (ulonglong2*)(smem + OFF_STG);
    ulonglong2* pLdT = (ulonglong2*)(smem + OFF_PLD);
    ulonglong2* pRuT = (ulonglong2*)(smem + OFF_PRU);
    float2*     pRLT = (float2*)(smem + OFF_PRL);
    ulonglong2* sBuT = (ulonglong2*)(smem + OFF_BUT);
    float*      sRd  = (float*)(smem + OFF_RRD);
    float*      sRu  = (float*)(smem + OFF_RRU);

    const int tid = threadIdx.x;
    const ulonglong2* Ld2 = (const ulonglong2*)Ld;
    const ulonglong2* Ru2 = (const ulonglong2*)Ru;
    const ulonglong2* bu2 = (const ulonglong2*)bu;

    for (int idx = tid; idx < 192; idx += NT) {
        int i = idx / 48, q = idx % 48;
        // stride-8 keyed tables (m = q/8, kk = q%8): granule q = kk + 8m
        int dst8 = (i*6 + (q >> 3))*8 + (q & 7);
        pLdT[dst8] = Ld2[idx];
        pRuT[dst8] = Ru2[idx];
        // z-keyed table (kk = q/6, j = q%6): scalar q = 6kk + j
        pRLT[(i*6 + (q % 6))*8 + (q / 6)] = make_float2(Rd[idx], Lu[idx]);
        // bias_u: sBuT[m*32 + l] = bu4[48*(l/8) + (l%8) + 8m]
        int m = idx / 32, ll = idx % 32;
        sBuT[idx] = bu2[48*(ll >> 3) + (ll & 7) + 8*m];
    }
    for (int idx = tid; idx < 64; idx += NT) {
        sRd[idx] = rule_d[idx];
        sRu[idx] = rule_u[idx];
    }
    __syncthreads();

    const int l = tid & 31;
    const int w = tid >> 5;
    const int g = l >> 3;        // group: a on input side, c on z/output side
    const int k = l & 7;

    float biasD[6];
#pragma unroll
    for (int j = 0; j < 6; j++)
        biasD[j] = bd[6*l + j];   // = bd[48g + 6k + j]

    const ulonglong2* x2 = (const ulonglong2*)x;
    char* outc = (char*)out;
    ulonglong2* stgW = stg + (size_t)w * (CHK * 192);
    const uint32_t stgW_s = (uint32_t)__cvta_generic_to_shared(stgW);

    const int gwarp = blockIdx.x * NW + w;
    const int nwarp = gridDim.x * NW;
    const int fbase = 48*g + k;  // lane's granule base (input AND output)

    for (int base = gwarp * TPI; base < ntok; base += nwarp * TPI) {
        // clamp trick: last quad may repeat token ntok-1 on input (harmless;
        // output is guarded)
        const int bc = (base + TPI <= ntok) ? base : (ntok - TPI);

        // ---- down stage 1: direct stride-8 loads (4 full 128B lines per
        //      LDG across the warp) + packed FMA ----
        u64 si2[TPI][4];
#pragma unroll
        for (int tt = 0; tt < TPI; tt++)
#pragma unroll
            for (int i = 0; i < 4; i++) si2[tt][i] = 0ull;

#pragma unroll
        for (int m = 0; m < 6; m++) {
            ulonglong2 u[TPI];
#pragma unroll
            for (int tt = 0; tt < TPI; tt++)
                u[tt] = x2[(size_t)(bc + tt) * 192 + fbase + 8*m];
#pragma unroll
            for (int i = 0; i < 4; i++) {
                ulonglong2 wv = pLdT[(i*6 + m)*8 + k];   // 1-wf broadcast
#pragma unroll
                for (int tt = 0; tt < TPI; tt++) {
                    si2[tt][i] = fma2(u[tt].x, wv.x, si2[tt][i]);
                    si2[tt][i] = fma2(u[tt].y, wv.y, si2[tt][i]);
                }
            }
        }
        // butterfly within 8-lane groups -> group-uniform si
        float si[TPI][4];
#pragma unroll
        for (int tt = 0; tt < TPI; tt++)
#pragma unroll
            for (int i = 0; i < 4; i++) {
                float v = sum2(si2[tt][i]);
                v += __shfl_xor_sync(0xffffffffu, v, 4);
                v += __shfl_xor_sync(0xffffffffu, v, 2);
                v += __shfl_xor_sync(0xffffffffu, v, 1);
                si[tt][i] = v;
            }

        // ---- down stage 2: weighted rotate (3 SHFL per i) ----
        float tD[TPI][4];
#pragma unroll
        for (int tt = 0; tt < TPI; tt++)
#pragma unroll
            for (int i = 0; i < 4; i++)
                tD[tt][i] = sRd[i*16 + 5*g] * si[tt][i];
#pragma unroll
        for (int m = 1; m < 4; m++)
#pragma unroll
            for (int i = 0; i < 4; i++) {
                float r = sRd[i*16 + ((g ^ m) << 2) + g];
#pragma unroll
                for (int tt = 0; tt < TPI; tt++)
                    tD[tt][i] = fmaf(r, __shfl_xor_sync(0xffffffffu, si[tt][i], m*8),
                                     tD[tt][i]);
            }

        // ---- fused z -> gelu_new -> up stage 1 (s2); lane z: q = 6k+j ----
        float s2[TPI][4];
#pragma unroll
        for (int tt = 0; tt < TPI; tt++)
#pragma unroll
            for (int i = 0; i < 4; i++) s2[tt][i] = 0.f;

#pragma unroll
        for (int j = 0; j < 6; j++) {
            float2 rl[4];
#pragma unroll
            for (int i = 0; i < 4; i++) rl[i] = pRLT[(i*6 + j)*8 + k];
            float zv[TPI];
#pragma unroll
            for (int tt = 0; tt < TPI; tt++) zv[tt] = biasD[j];
#pragma unroll
            for (int i = 0; i < 4; i++)
#pragma unroll
                for (int tt = 0; tt < TPI; tt++)
                    zv[tt] = fmaf(tD[tt][i], rl[i].x, zv[tt]);
#pragma unroll
            for (int tt = 0; tt < TPI; tt++) {
                float z   = zv[tt];
                float arg = 0.7978845608028654f * fmaf(0.044715f*z, z*z, z);
                float h   = 0.5f * z;
                zv[tt] = fmaf(h, tanh_fast(arg), h);   // 0.5z(1+tanh)
            }
#pragma unroll
            for (int i = 0; i < 4; i++)
#pragma unroll
                for (int tt = 0; tt < TPI; tt++)
                    s2[tt][i] = fmaf(zv[tt], rl[i].y, s2[tt][i]);
        }
        // butterfly -> group-uniform s2
#pragma unroll
        for (int tt = 0; tt < TPI; tt++)
#pragma unroll
            for (int i = 0; i < 4; i++) {
                float v = s2[tt][i];
                v += __shfl_xor_sync(0xffffffffu, v, 4);
                v += __shfl_xor_sync(0xffffffffu, v, 2);
                v += __shfl_xor_sync(0xffffffffu, v, 1);
                s2[tt][i] = v;
            }

        // ---- up stage 2: weighted rotate ----
        float tU[TPI][4];
#pragma unroll
        for (int tt = 0; tt < TPI; tt++)
#pragma unroll
            for (int i = 0; i < 4; i++)
                tU[tt][i] = sRu[i*16 + 5*g] * s2[tt][i];
#pragma unroll
        for (int m = 1; m < 4; m++)
#pragma unroll
            for (int i = 0; i < 4; i++) {
                float r = sRu[i*16 + ((g ^ m) << 2) + g];
#pragma unroll
                for (int tt = 0; tt < TPI; tt++)
                    tU[tt][i] = fmaf(r, __shfl_xor_sync(0xffffffffu, s2[tt][i], m*8),
                                     tU[tt][i]);
            }

        // ---- output chunks: stride-8 compute -> linear conflict-free STS
        //      (bias folded in) -> TMA bulk store ----
#pragma unroll
        for (int c0 = 0; c0 < TPI; c0 += CHK) {
            u64 tUp[CHK][4];
#pragma unroll
            for (int cc = 0; cc < CHK; cc++)
#pragma unroll
                for (int i = 0; i < 4; i++)
                    tUp[cc][i] = pk2(tU[c0+cc][i], tU[c0+cc][i]);

            // previous use of these slots must be drained by the engine
            if (l == 0)
                asm volatile("cp.async.bulk.wait_group.read 0;" ::: "memory");
            __syncwarp();

#pragma unroll
            for (int m = 0; m < 6; m++) {
                ulonglong2 rv[4];
#pragma unroll
                for (int i = 0; i < 4; i++) rv[i] = pRuT[(i*6 + m)*8 + k];
                ulonglong2 bb = sBuT[m*32 + l];
#pragma unroll
                for (int cc = 0; cc < CHK; cc++) {
                    ulonglong2 o = bb;
#pragma unroll
                    for (int i = 0; i < 4; i++) {
                        o.x = fma2(tUp[cc][i], rv[i].x, o.x);
                        o.y = fma2(tUp[cc][i], rv[i].y, o.y);
                    }
                    stgW[cc*192 + fbase + 8*m] = o;      // linear, conflict-free
                }
            }
            __syncwarp();
            asm volatile("fence.proxy.async.shared::cta;" ::: "memory");
            if (l == 0) {
                int t0 = bc + c0;
                if (t0 + 1 < ntok)          // both tokens: one 6144B store
                    bulk_store(outc + (size_t)t0 * 3072, stgW_s, 6144);
                else if (t0 < ntok)
                    bulk_store(outc + (size_t)t0 * 3072, stgW_s, 3072);
                asm volatile("cp.async.bulk.commit_group;" ::: "memory");
            }
        }
    }
    // drain outstanding bulk stores before exit
    if (l == 0)
        asm volatile("cp.async.bulk.wait_group 0;" ::: "memory");
}

extern "C" void kernel_launch(void* const* d_in, const int* in_sizes, int n_in,
                              void* d_out, int out_size)
{
    const float* x      = (const float*)d_in[0];
    const float* rule_d = (const float*)d_in[1];
    const float* Ld     = (const float*)d_in[2];
    const float* Rd     = (const float*)d_in[3];
    const float* bd     = (const float*)d_in[4];
    const float* rule_u = (const float*)d_in[5];
    const float* Lu     = (const float*)d_in[6];
    const float* Ru     = (const float*)d_in[7];
    const float* bu     = (const float*)d_in[8];

    const int ntok = in_sizes[0] / 768;

    cudaFuncSetAttribute(phm_fused_kernel,
                         cudaFuncAttributeMaxDynamicSharedMemorySize,
                         SMEM_TOTAL);

    // occupancy-adaptive one-wave grid on the REAL SM count (GB300 = 152)
    int smCount = 152, occ = 5;
    cudaDeviceGetAttribute(&smCount, cudaDevAttrMultiProcessorCount, 0);
    cudaOccupancyMaxActiveBlocksPerMultiprocessor(&occ, phm_fused_kernel,
                                                  NT, SMEM_TOTAL);
    if (occ < 1) occ = 1;
    int grid = smCount * occ;

    phm_fused_kernel<<<grid, NT, SMEM_TOTAL>>>(x, rule_d, Ld, Rd, bd,
                                               rule_u, Lu, Ru, bu,
                                               (float*)d_out, ntok);
}